// round 5
// baseline (speedup 1.0000x reference)
#include <cuda_runtime.h>

#define NB     2048
#define NOH    20
#define NOTH   23
#define NC     10
#define SC     200      // NOH*NC
#define EMB    9
#define OUTC   32
#define XSTR   43       // NOH + NOTH
#define HW     2304     // 48*48
#define SLABSZ 73728    // OUTC*HW floats per batch

// Dynamic smem layout (float offsets)
#define OFF_FCW   0                      // 1800 floats
#define OFF_W     1800                   // 1024 floats
#define OFF_CB    2824                   // 32 floats
#define OFF_V     2856                   // 2048*9 = 18432 floats (v[b][e] flat)
#define OFF_TILE  21288                  // 4*2304 = 9216 floats
#define SMEM_FLOATS 30504                // 122016 bytes

// Single fused, single-wave kernel.
// Grid (c 0..7, og 0..7, bs 0..1) = 128 CTAs x 512 threads.
// CTA computes channels [og*4, og*4+4) x all m for residue class c, then
// stores that 36 KB-contiguous tile for 128 batches b = c + 8*(bs*128+u).
//
// Verified identities (rel_err ~1.4e-7, R1-R4):
//   out[b][o][m] depends on b only through c = b & 7
//   three 1x1 convs fold into one 32x32 weight W + bias cb
//   slab[c][o][m] = cb[o] + sum_i W[o,i]  * v[256*((c+i)&7)+q, r]   (q=m/9, r=m%9)
//                         + sum_j W[o,9+j]* x[bb_j*43+20+(4j+m)%23],
//                           bb_j = (256c + (2304j+m)/23) & 2047
__global__ void __launch_bounds__(512) k_fused(
    const float* __restrict__ x,
    const float* __restrict__ fc_w, const float* __restrict__ fc_b,
    const float* __restrict__ oh_w, const float* __restrict__ oh_b,
    const float* __restrict__ ot_w, const float* __restrict__ ot_b,
    const float* __restrict__ all_w, const float* __restrict__ all_b,
    float* __restrict__ out)
{
    extern __shared__ __align__(16) float sm[];
    float* s_fcw  = sm + OFF_FCW;
    float* s_W    = sm + OFF_W;
    float* s_cb   = sm + OFF_CB;
    float* s_v    = sm + OFF_V;     // flat: v[b*9 + e]
    float* s_tile = sm + OFF_TILE;  // [ch][m] = ch*2304 + m

    const int t  = threadIdx.x;     // 0..511
    const int c  = blockIdx.x;      // 0..7
    const int og = blockIdx.y;      // 0..7  -> channels og*4 .. og*4+3
    const int bs = blockIdx.z;      // 0..1

    // ---- stage fc_w --------------------------------------------------------
    for (int i = t; i < EMB * SC; i += 512) s_fcw[i] = fc_w[i];

    // ---- fold the three convs into one 32x32 weight + bias -----------------
    for (int idx = t; idx < OUTC * 32; idx += 512) {
        int o = idx >> 5, i = idx & 31;
        float s = 0.f;
        if (i < EMB) {
            #pragma unroll
            for (int cc = 0; cc < EMB; cc++)
                s += all_w[o * 32 + cc] * oh_w[cc * EMB + i];
        } else {
            int j = i - EMB;
            #pragma unroll
            for (int cc = 0; cc < NOTH; cc++)
                s += all_w[o * 32 + EMB + cc] * ot_w[cc * NOTH + j];
        }
        s_W[idx] = s;
    }
    if (t < OUTC) {
        float cb = all_b[t];
        #pragma unroll
        for (int cc = 0; cc < EMB; cc++)  cb += all_w[t * 32 + cc] * oh_b[cc];
        #pragma unroll
        for (int cc = 0; cc < NOTH; cc++) cb += all_w[t * 32 + EMB + cc] * ot_b[cc];
        s_cb[t] = cb;
    }
    __syncthreads();    // s_fcw ready

    // ---- all 2048 embedding rows: v[b][e] (thread t -> rows t+512i) --------
    #pragma unroll
    for (int i = 0; i < 4; i++) {
        int b = t + 512 * i;
        const float* xr = x + b * XSTR;
        float acc[EMB];
        #pragma unroll
        for (int e = 0; e < EMB; e++) acc[e] = fc_b[e];
        #pragma unroll
        for (int j = 0; j < NOH; j++) {
            int id   = (int)xr[j];
            int base = j * NC + id;
            #pragma unroll
            for (int e = 0; e < EMB; e++) acc[e] += s_fcw[e * SC + base];
        }
        #pragma unroll
        for (int e = 0; e < EMB; e++) s_v[b * EMB + e] = acc[e];
    }
    __syncthreads();    // s_W, s_cb, s_v ready

    // ---- compute tile: channels og*4..og*4+3, all m. thread -> m = t+512i --
    const int o0 = og * 4;
    #pragma unroll
    for (int mi = 0; mi < 5; mi++) {
        int m = t + 512 * mi;
        if (m >= HW) break;
        int q = m / 9;
        int r = m - 9 * q;

        float g[32];
        #pragma unroll
        for (int i = 0; i < 9; i++)
            g[i] = s_v[(256 * ((c + i) & 7) + q) * EMB + r];
        #pragma unroll
        for (int j = 0; j < 23; j++) {
            int eo = (4 * j + m) % 23;
            int T  = (2304 * j + m) / 23;
            int bb = (256 * c + T) & 2047;
            g[9 + j] = x[bb * XSTR + NOH + eo];
        }

        #pragma unroll
        for (int ch = 0; ch < 4; ch++) {
            int o = o0 + ch;
            const float4* W4 = (const float4*)(s_W + o * 32);
            float s = s_cb[o];
            #pragma unroll
            for (int j4 = 0; j4 < 8; j4++) {
                float4 w = W4[j4];
                s += w.x * g[4 * j4]     + w.y * g[4 * j4 + 1]
                   + w.z * g[4 * j4 + 2] + w.w * g[4 * j4 + 3];
            }
            s_tile[ch * HW + m] = s;
        }
    }
    __syncthreads();    // tile ready (9216 floats = 2304 float4)

    // ---- stage tile in registers: float4 idx f = t + 512i ------------------
    const float4* tile4 = (const float4*)s_tile;
    float4 r0 = tile4[t];
    float4 r1 = tile4[t + 512];
    float4 r2 = tile4[t + 1024];
    float4 r3 = tile4[t + 1536];
    float4 r4;
    const bool has5 = (t < 256);            // t+2048 < 2304
    if (has5) r4 = tile4[t + 2048];

    // ---- store phase: 36 KB contiguous per batch, 128 batches --------------
    // out float4 base for batch b: b*18432 + og*2304
    const float4* dummy = tile4; (void)dummy;
    float4* __restrict__ out4 = (float4*)out
        + (size_t)(c + 1024 * bs) * (SLABSZ / 4) + (size_t)og * (HW * 4 / 4);

    #pragma unroll 4
    for (int u = 0; u < 128; u++) {
        float4* __restrict__ dst = out4 + (size_t)u * (8 * SLABSZ / 4);
        dst[t]        = r0;
        dst[t + 512]  = r1;
        dst[t + 1024] = r2;
        dst[t + 1536] = r3;
        if (has5) dst[t + 2048] = r4;
    }
}

// ---------------------------------------------------------------------------
extern "C" void kernel_launch(void* const* d_in, const int* in_sizes, int n_in,
                              void* d_out, int out_size) {
    const float* x     = (const float*)d_in[0];
    const float* fc_w  = (const float*)d_in[1];
    const float* fc_b  = (const float*)d_in[2];
    const float* oh_w  = (const float*)d_in[3];
    const float* oh_b  = (const float*)d_in[4];
    const float* ot_w  = (const float*)d_in[5];
    const float* ot_b  = (const float*)d_in[6];
    const float* all_w = (const float*)d_in[7];
    const float* all_b = (const float*)d_in[8];
    float* out = (float*)d_out;

    cudaFuncSetAttribute(k_fused, cudaFuncAttributeMaxDynamicSharedMemorySize,
                         SMEM_FLOATS * sizeof(float));

    dim3 grid(8, 8, 2);   // (c, og, bs) = 128 CTAs, single wave
    k_fused<<<grid, 512, SMEM_FLOATS * sizeof(float)>>>(
        x, fc_w, fc_b, oh_w, oh_b, ot_w, ot_b, all_w, all_b, out);
}

// round 6
// speedup vs baseline: 1.4730x; 1.4730x over previous
#include <cuda_runtime.h>

#define NB     2048
#define NOH    20
#define NOTH   23
#define NC     10
#define SC     200      // NOH*NC
#define EMB    9
#define OUTC   32
#define XSTR   43       // NOH + NOTH
#define HW     2304     // 48*48
#define SLABSZ 73728    // OUTC*HW floats per batch

// Device scratch (allocation-free)
__device__ float g_v[NB * EMB];      // embedding vectors
__device__ float g_W[OUTC * 32];     // fused weight
__device__ float g_cb[OUTC];         // fused bias

// ---------------------------------------------------------------------------
// k1: grid 17 CTAs x 128 threads.
//  CTAs 0..15: compute g_v for rows [cta*128, cta*128+128) with coalesced x staging.
//  CTA 16:     fold the three 1x1 convs into g_W / g_cb.
__global__ void __launch_bounds__(128) k_pre(
    const float* __restrict__ x,
    const float* __restrict__ fc_w, const float* __restrict__ fc_b,
    const float* __restrict__ oh_w, const float* __restrict__ oh_b,
    const float* __restrict__ ot_w, const float* __restrict__ ot_b,
    const float* __restrict__ all_w, const float* __restrict__ all_b)
{
    const int t = threadIdx.x;

    if (blockIdx.x == 16) {
        // weight fold (tiny)
        for (int idx = t; idx < OUTC * 32; idx += 128) {
            int o = idx >> 5, i = idx & 31;
            float s = 0.f;
            if (i < EMB) {
                #pragma unroll
                for (int cc = 0; cc < EMB; cc++)
                    s += all_w[o * 32 + cc] * oh_w[cc * EMB + i];
            } else {
                int j = i - EMB;
                #pragma unroll
                for (int cc = 0; cc < NOTH; cc++)
                    s += all_w[o * 32 + EMB + cc] * ot_w[cc * NOTH + j];
            }
            g_W[idx] = s;
        }
        if (t < OUTC) {
            float cb = all_b[t];
            #pragma unroll
            for (int cc = 0; cc < EMB; cc++)  cb += all_w[t * 32 + cc] * oh_b[cc];
            #pragma unroll
            for (int cc = 0; cc < NOTH; cc++) cb += all_w[t * 32 + EMB + cc] * ot_b[cc];
            g_cb[t] = cb;
        }
        return;
    }

    __shared__ __align__(16) float s_fcw[EMB * SC];      // 7.2 KB
    __shared__ __align__(16) float s_x[128 * XSTR];      // 22 KB, this CTA's x rows

    // coalesced stages
    for (int i = t; i < EMB * SC; i += 128) s_fcw[i] = fc_w[i];
    const int b0 = blockIdx.x * 128;
    {   // 128*43 floats = 1376 float4, base is 16B-aligned (b0*43*4 % 16 == 0)
        const float4* src = (const float4*)(x + (size_t)b0 * XSTR);
        float4* dst = (float4*)s_x;
        for (int i = t; i < 128 * XSTR / 4; i += 128) dst[i] = src[i];
    }
    __syncthreads();

    // one row per thread, indices from smem
    const float* xr = s_x + t * XSTR;
    float acc[EMB];
    #pragma unroll
    for (int e = 0; e < EMB; e++) acc[e] = fc_b[e];
    #pragma unroll
    for (int j = 0; j < NOH; j++) {
        int id   = (int)xr[j];
        int base = j * NC + id;
        #pragma unroll
        for (int e = 0; e < EMB; e++) acc[e] += s_fcw[e * SC + base];
    }
    #pragma unroll
    for (int e = 0; e < EMB; e++) g_v[(b0 + t) * EMB + e] = acc[e];
}

// ---------------------------------------------------------------------------
// k2: slab compute + replicate.  Grid (c:8, og:8, bs:2) = 128 CTAs x 576 thr.
// CTA computes channels [og*4, og*4+4) x all 2304 m for residue class c
// (36 KB contiguous in the output), then stores it for 128 batches
// b = c + 8*(bs*128 + u).
//
// Verified identities (rel_err ~1.4e-7, R1-R5):
//   out[b][o][m] depends on b only through c = b & 7
//   slab[c][o][m] = cb[o] + sum_i W[o,i]  * v[256*((c+i)&7)+q, r]  (q=m/9, r=m%9)
//                         + sum_j W[o,9+j]* x[bb_j*43+20+(4j+m)%23],
//                           bb_j = (256c + (2304j+m)/23) & 2047
#define K2_THREADS 576
// dynamic smem layout (floats)
#define OFF_V     0                   // 18432
#define OFF_W     18432               // 1024
#define OFF_CB    19456               // 32
#define OFF_TILE  19488               // 9216
#define K2_SMEM_FLOATS 28704          // 114816 bytes

__global__ void __launch_bounds__(K2_THREADS) k_main(
    const float* __restrict__ x, float* __restrict__ out)
{
    extern __shared__ __align__(16) float sm[];
    float* s_v    = sm + OFF_V;     // v[b*9+e]
    float* s_W    = sm + OFF_W;
    float* s_cb   = sm + OFF_CB;
    float* s_tile = sm + OFF_TILE;  // [ch][m]

    const int t  = threadIdx.x;     // 0..575
    const int c  = blockIdx.x;      // 0..7
    const int og = blockIdx.y;      // 0..7
    const int bs = blockIdx.z;      // 0..1

    // ---- coalesced stages (all precomputed by k1) --------------------------
    {
        const float4* src = (const float4*)g_v;
        float4* dst = (float4*)s_v;
        for (int i = t; i < NB * EMB / 4; i += K2_THREADS) dst[i] = src[i];
        const float4* ws = (const float4*)g_W;
        float4* wd = (float4*)s_W;
        for (int i = t; i < OUTC * 32 / 4; i += K2_THREADS) wd[i] = ws[i];
        if (t < OUTC) s_cb[t] = g_cb[t];
    }
    __syncthreads();

    // ---- compute tile: thread -> m = t + 576*mi, 4 channels ---------------
    const int o0 = og * 4;
    #pragma unroll
    for (int mi = 0; mi < 4; mi++) {
        int m = t + K2_THREADS * mi;
        int q = m / 9;
        int r = m - 9 * q;

        float g[32];
        #pragma unroll
        for (int i = 0; i < 9; i++)
            g[i] = s_v[(256 * ((c + i) & 7) + q) * EMB + r];
        #pragma unroll
        for (int j = 0; j < 23; j++) {
            int eo = (4 * j + m) % 23;
            int T  = (2304 * j + m) / 23;
            int bb = (256 * c + T) & 2047;
            g[9 + j] = x[bb * XSTR + NOH + eo];
        }

        #pragma unroll
        for (int ch = 0; ch < 4; ch++) {
            int o = o0 + ch;
            const float4* W4 = (const float4*)(s_W + o * 32);
            float s = s_cb[o];
            #pragma unroll
            for (int j4 = 0; j4 < 8; j4++) {
                float4 w = W4[j4];
                s += w.x * g[4 * j4]     + w.y * g[4 * j4 + 1]
                   + w.z * g[4 * j4 + 2] + w.w * g[4 * j4 + 3];
            }
            s_tile[ch * HW + m] = s;
        }
    }
    __syncthreads();

    // ---- stage tile in registers (2304 float4 = 576 threads x 4) ----------
    const float4* tile4 = (const float4*)s_tile;
    float4 r0 = tile4[t];
    float4 r1 = tile4[t + 576];
    float4 r2 = tile4[t + 1152];
    float4 r3 = tile4[t + 1728];

    // ---- store: 36 KB contiguous per batch, 128 batches --------------------
    float4* __restrict__ out4 = (float4*)out
        + (size_t)(c + 8 * (bs * 128)) * (SLABSZ / 4)
        + (size_t)og * 2304;          // og*4 channels * 2304 m / 4

    #pragma unroll 8
    for (int u = 0; u < 128; u++) {
        float4* __restrict__ dst = out4 + (size_t)u * (8 * SLABSZ / 4);
        dst[t]        = r0;
        dst[t + 576]  = r1;
        dst[t + 1152] = r2;
        dst[t + 1728] = r3;
    }
}

// ---------------------------------------------------------------------------
extern "C" void kernel_launch(void* const* d_in, const int* in_sizes, int n_in,
                              void* d_out, int out_size) {
    const float* x     = (const float*)d_in[0];
    const float* fc_w  = (const float*)d_in[1];
    const float* fc_b  = (const float*)d_in[2];
    const float* oh_w  = (const float*)d_in[3];
    const float* oh_b  = (const float*)d_in[4];
    const float* ot_w  = (const float*)d_in[5];
    const float* ot_b  = (const float*)d_in[6];
    const float* all_w = (const float*)d_in[7];
    const float* all_b = (const float*)d_in[8];
    float* out = (float*)d_out;

    cudaFuncSetAttribute(k_main, cudaFuncAttributeMaxDynamicSharedMemorySize,
                         K2_SMEM_FLOATS * sizeof(float));

    k_pre<<<17, 128>>>(x, fc_w, fc_b, oh_w, oh_b, ot_w, ot_b, all_w, all_b);
    dim3 grid(8, 8, 2);   // 128 CTAs, single wave
    k_main<<<grid, K2_THREADS, K2_SMEM_FLOATS * sizeof(float)>>>(x, out);
}